// round 9
// baseline (speedup 1.0000x reference)
#include <cuda_runtime.h>

// ---------------- fixed problem shape ----------------
#define E_TOT 262144
#define N_TOT 16384

// ---------------- device scratch (static, no allocation) ----------------
__device__ float g_M   [64 * 2048];                 // Wq(x)Wk contraction
__device__ float g_P   [(size_t)N_TOT * 2048];      // per-node logit matrix
__device__ float g_envn[(size_t)N_TOT * 128];
__device__ float g_We  [(size_t)E_TOT * 64];
__device__ float g_tpo [(size_t)E_TOT * 256];
__device__ float g_s2  [(size_t)E_TOT * 64];
__device__ int   g_cnt [N_TOT];
__device__ int   g_offs[N_TOT + 1];
__device__ int   g_wo  [N_TOT];
__device__ int   g_elist[E_TOT];

typedef unsigned long long u64;

static __device__ __forceinline__ u64 dup2(float a) {
    u64 r; asm("mov.b64 %0, {%1, %1};" : "=l"(r) : "f"(a)); return r;
}
static __device__ __forceinline__ void fma2(u64& acc, u64 a, u64 b) {
    asm("fma.rn.f32x2 %0, %1, %2, %0;" : "+l"(acc) : "l"(a), "l"(b));
}
static __device__ __forceinline__ float lo2(u64 v) { return __uint_as_float((unsigned)v); }
static __device__ __forceinline__ float hi2(u64 v) { return __uint_as_float((unsigned)(v >> 32)); }
static __device__ __forceinline__ float silu_f(float v) { return v / (1.0f + __expf(-v)); }

// ---------------- CSR build ----------------
__global__ void k_count(const int* __restrict__ src, int* __restrict__ cnt) {
    int e = blockIdx.x * 256 + threadIdx.x;
    atomicAdd(&cnt[src[e]], 1);
}

__global__ void __launch_bounds__(1024) k_scan(const int* __restrict__ cnt,
                                               int* __restrict__ offs,
                                               int* __restrict__ wo) {
    __shared__ int part[1024];
    const int t = threadIdx.x;
    const int base = t * 16;
    int loc[16];
    int s = 0;
#pragma unroll
    for (int i = 0; i < 16; i++) { loc[i] = s; s += cnt[base + i]; }
    part[t] = s;
    __syncthreads();
    for (int d = 1; d < 1024; d <<= 1) {
        int v = part[t];
        int u = (t >= d) ? part[t - d] : 0;
        __syncthreads();
        part[t] = v + u;
        __syncthreads();
    }
    int tOff = part[t] - s;   // exclusive prefix for this thread
#pragma unroll
    for (int i = 0; i < 16; i++) {
        int o = tOff + loc[i];
        offs[base + i] = o;
        wo[base + i] = o;
    }
    if (t == 1023) offs[N_TOT] = part[1023];
}

__global__ void k_scatter(const int* __restrict__ src, int* __restrict__ wo,
                          int* __restrict__ elist) {
    int e = blockIdx.x * 256 + threadIdx.x;
    int pos = atomicAdd(&wo[src[e]], 1);
    elist[pos] = e;
}

// ---------------- K0: M[c, j*32+m] = sum_d Wq[c,16m+d]*Wk[j,16m+d] ----------------
__global__ void k_M(const float* __restrict__ Wq, const float* __restrict__ Wk,
                    float* __restrict__ M) {
    const int c = blockIdx.x;
    const int t = threadIdx.x;
    const int j = t >> 2;
    const int mg = (t & 3) * 8;
    const float* wq = Wq + (size_t)c * 512;
    const float* wk = Wk + (size_t)j * 512;
#pragma unroll
    for (int mm = 0; mm < 8; mm++) {
        int m = mg + mm;
        float s = 0.f;
#pragma unroll
        for (int d = 0; d < 16; d++) s = fmaf(wq[16 * m + d], wk[16 * m + d], s);
        M[(size_t)c * 2048 + j * 32 + m] = s;
    }
}

// ---------------- G1: P = node_attrs @ M   [16384,64]x[64,2048] ----------------
__global__ void __launch_bounds__(256) g_pmat(const float* __restrict__ A,
                                              const float* __restrict__ M,
                                              float* __restrict__ P) {
    extern __shared__ float sm[];
    float (*As)[132] = (float(*)[132])sm;
    float (*Bs)[132] = (float(*)[132])(sm + 64 * 132);
    const int t = threadIdx.x;
    const size_t n0 = (size_t)blockIdx.x * 128;
    const int cb = blockIdx.y * 128;
    for (int i = t; i < 64 * 32; i += 256) {
        int k = i >> 5, c = (i & 31) * 4;
        *(float4*)&Bs[k][c] = *(const float4*)&M[(size_t)k * 2048 + cb + c];
    }
    for (int i = t; i < 128 * 16; i += 256) {
        int r = i >> 4, k = (i & 15) * 4;
        float4 v = *(const float4*)&A[(n0 + r) * 64 + k];
        As[k][r] = v.x; As[k + 1][r] = v.y; As[k + 2][r] = v.z; As[k + 3][r] = v.w;
    }
    __syncthreads();
    const int tx = t & 15, ty = t >> 4;
    const int c0 = tx * 8, r0 = ty * 8;
    u64 acc[8][4];
#pragma unroll
    for (int i = 0; i < 8; i++)
#pragma unroll
        for (int j = 0; j < 4; j++) acc[i][j] = 0ull;
#pragma unroll 4
    for (int k = 0; k < 64; k++) {
        float4 a0 = *(float4*)&As[k][r0], a1 = *(float4*)&As[k][r0 + 4];
        ulonglong2 b0 = *(ulonglong2*)&Bs[k][c0];
        ulonglong2 b1 = *(ulonglong2*)&Bs[k][c0 + 4];
        float av[8] = {a0.x, a0.y, a0.z, a0.w, a1.x, a1.y, a1.z, a1.w};
#pragma unroll
        for (int i = 0; i < 8; i++) {
            u64 ad = dup2(av[i]);
            fma2(acc[i][0], ad, b0.x); fma2(acc[i][1], ad, b0.y);
            fma2(acc[i][2], ad, b1.x); fma2(acc[i][3], ad, b1.y);
        }
    }
#pragma unroll
    for (int i = 0; i < 8; i++) {
        size_t n = n0 + r0 + i;
        *(float4*)&P[n * 2048 + cb + c0] =
            make_float4(lo2(acc[i][0]), hi2(acc[i][0]), lo2(acc[i][1]), hi2(acc[i][1]));
        *(float4*)&P[n * 2048 + cb + c0 + 4] =
            make_float4(lo2(acc[i][2]), hi2(acc[i][2]), lo2(acc[i][3]), hi2(acc[i][3]));
    }
}

// ---------------- fused attention: one warp per node ----------------
// logits + exp + softmax-weighted env sum + divide + SO3 layernorm, all in registers
__global__ void __launch_bounds__(128) k_attn(const float* __restrict__ scal,
                                              const float* __restrict__ P,
                                              const float* __restrict__ We,
                                              const float* __restrict__ equiv,
                                              const int* __restrict__ offs,
                                              const int* __restrict__ elist,
                                              const float* __restrict__ genv,
                                              float* __restrict__ envn) {
    const int n = blockIdx.x * 4 + (threadIdx.x >> 5);
    const int m = threadIdx.x & 31;
    const int o0 = offs[n], o1 = offs[n + 1];
    if (o0 == o1) return;
    // P row for this node, lane m holds column j*32+m for j=0..63
    float Preg[64];
    const float* p = P + (size_t)n * 2048 + m;
#pragma unroll
    for (int j = 0; j < 64; j++) Preg[j] = __ldg(&p[j * 32]);

    float den = 0.f, x0 = 0.f, x1 = 0.f, x2 = 0.f, x3 = 0.f;

    // software-pipelined edge loop
    int e = elist[o0];
    float slo = scal[(size_t)e * 64 + m];
    float shi = scal[(size_t)e * 64 + 32 + m];
    float2 w  = *(const float2*)&We[(size_t)e * 64 + 2 * m];
    float4 ev = *(const float4*)&equiv[(size_t)e * 128 + 4 * m];
    for (int i = o0; i < o1; i++) {
        float cslo = slo, cshi = shi;
        float2 cw = w; float4 cev = ev;
        if (i + 1 < o1) {
            int en = elist[i + 1];
            slo = scal[(size_t)en * 64 + m];
            shi = scal[(size_t)en * 64 + 32 + m];
            w   = *(const float2*)&We[(size_t)en * 64 + 2 * m];
            ev  = *(const float4*)&equiv[(size_t)en * 128 + 4 * m];
        }
        float a0 = 0.f, a1 = 0.f, a2 = 0.f, a3 = 0.f;
#pragma unroll
        for (int j = 0; j < 32; j += 4) {
            a0 = fmaf(__shfl_sync(0xffffffffu, cslo, j),     Preg[j],     a0);
            a1 = fmaf(__shfl_sync(0xffffffffu, cslo, j + 1), Preg[j + 1], a1);
            a2 = fmaf(__shfl_sync(0xffffffffu, cslo, j + 2), Preg[j + 2], a2);
            a3 = fmaf(__shfl_sync(0xffffffffu, cslo, j + 3), Preg[j + 3], a3);
        }
#pragma unroll
        for (int j = 0; j < 32; j += 4) {
            a0 = fmaf(__shfl_sync(0xffffffffu, cshi, j),     Preg[32 + j],     a0);
            a1 = fmaf(__shfl_sync(0xffffffffu, cshi, j + 1), Preg[33 + j],     a1);
            a2 = fmaf(__shfl_sync(0xffffffffu, cshi, j + 2), Preg[34 + j],     a2);
            a3 = fmaf(__shfl_sync(0xffffffffu, cshi, j + 3), Preg[35 + j],     a3);
        }
        float lg = (a0 + a1 + a2 + a3) * 0.25f;         // INV_SQRTD
        lg = fminf(5.0f, fmaxf(-5.0f, lg));             // CLIP
        float el = __expf(lg);                          // clipped: no max-shift needed
        den += el;
        float w0 = cw.x * el, w1 = cw.y * el;           // ENV_BLOCKS = (1,3)
        x0 = fmaf(cev.x, w0, x0);
        x1 = fmaf(cev.y, w1, x1);
        x2 = fmaf(cev.z, w1, x2);
        x3 = fmaf(cev.w, w1, x3);
    }
    float inv = __frcp_rn(den);   // deg>=1 -> den >= e^-5 > 0
    x0 *= inv; x1 *= inv; x2 *= inv; x3 *= inv;
    float s0 = x0 * x0;
    float s1 = x1 * x1 + x2 * x2 + x3 * x3;
#pragma unroll
    for (int o = 16; o; o >>= 1) {
        s0 += __shfl_xor_sync(0xffffffffu, s0, o);
        s1 += __shfl_xor_sync(0xffffffffu, s1, o);
    }
    float i0 = rsqrtf(s0 * (1.f / 32.f) + 1e-6f);
    float i1 = rsqrtf(s1 * (1.f / 96.f) + 1e-6f);
    float g0 = genv[2 * m], g1 = genv[2 * m + 1];
    *(float4*)&envn[(size_t)n * 128 + 4 * m] =
        make_float4(x0 * i0 * g0, x1 * i1 * g1, x2 * i1 * g1, x3 * i1 * g1);
}

// ---------------- fused env MLP: We = silu([scal|cond]@W1+b1) @ W2 ----------------
#define R2_OFF 16896
#define SMF ((16896 + 12672) * 4)

__global__ void __launch_bounds__(256) g_env_f(const float* __restrict__ X64,
                                               const float* __restrict__ C32,
                                               const float* __restrict__ W1,
                                               const float* __restrict__ b1,
                                               const float* __restrict__ W2,
                                               float* __restrict__ We) {
    extern __shared__ float sm[];
    float (*As)[132] = (float(*)[132])sm;
    float (*Bs)[132] = (float(*)[132])(sm + R2_OFF);
    float (*H)[132]  = (float(*)[132])sm;
    float (*B2)[68]  = (float(*)[68])(sm + R2_OFF);
    const int t = threadIdx.x;
    const size_t e0 = (size_t)blockIdx.x * 128;
    for (int i = t; i < 96 * 32; i += 256) {
        int k = i >> 5, c = (i & 31) * 4;
        *(float4*)&Bs[k][c] = *(const float4*)&W1[k * 128 + c];
    }
    for (int i = t; i < 128 * 16; i += 256) {
        int r = i >> 4, k = (i & 15) * 4;
        float4 v = *(const float4*)&X64[(e0 + r) * 64 + k];
        As[k][r] = v.x; As[k + 1][r] = v.y; As[k + 2][r] = v.z; As[k + 3][r] = v.w;
    }
    for (int i = t; i < 128 * 8; i += 256) {
        int r = i >> 3, k = (i & 7) * 4;
        float4 v = *(const float4*)&C32[(e0 + r) * 32 + k];
        As[64 + k][r] = v.x; As[65 + k][r] = v.y; As[66 + k][r] = v.z; As[67 + k][r] = v.w;
    }
    __syncthreads();
    const int tx = t & 15, ty = t >> 4;
    const int c0 = tx * 8, r0 = ty * 8;
    u64 acc[8][4];
#pragma unroll
    for (int i = 0; i < 8; i++)
#pragma unroll
        for (int j = 0; j < 4; j++) acc[i][j] = 0ull;
#pragma unroll 4
    for (int k = 0; k < 96; k++) {
        float4 a0 = *(float4*)&As[k][r0], a1 = *(float4*)&As[k][r0 + 4];
        ulonglong2 b0 = *(ulonglong2*)&Bs[k][c0];
        ulonglong2 b1 = *(ulonglong2*)&Bs[k][c0 + 4];
        float av[8] = {a0.x, a0.y, a0.z, a0.w, a1.x, a1.y, a1.z, a1.w};
#pragma unroll
        for (int i = 0; i < 8; i++) {
            u64 ad = dup2(av[i]);
            fma2(acc[i][0], ad, b0.x); fma2(acc[i][1], ad, b0.y);
            fma2(acc[i][2], ad, b1.x); fma2(acc[i][3], ad, b1.y);
        }
    }
    float bb[8];
#pragma unroll
    for (int j = 0; j < 8; j++) bb[j] = b1[c0 + j];
    float hbuf[8][8];
#pragma unroll
    for (int i = 0; i < 8; i++)
#pragma unroll
        for (int j = 0; j < 4; j++) {
            hbuf[i][2 * j]     = silu_f(lo2(acc[i][j]) + bb[2 * j]);
            hbuf[i][2 * j + 1] = silu_f(hi2(acc[i][j]) + bb[2 * j + 1]);
        }
    __syncthreads();
#pragma unroll
    for (int i = 0; i < 8; i++) {
        *(float4*)&H[r0 + i][c0]     = make_float4(hbuf[i][0], hbuf[i][1], hbuf[i][2], hbuf[i][3]);
        *(float4*)&H[r0 + i][c0 + 4] = make_float4(hbuf[i][4], hbuf[i][5], hbuf[i][6], hbuf[i][7]);
    }
    for (int i = t; i < 128 * 16; i += 256) {
        int k = i >> 4, c = (i & 15) * 4;
        *(float4*)&B2[k][c] = *(const float4*)&W2[k * 64 + c];
    }
    __syncthreads();
    const int c2 = tx * 4;
    u64 acc2[8][2];
#pragma unroll
    for (int i = 0; i < 8; i++) { acc2[i][0] = 0ull; acc2[i][1] = 0ull; }
#pragma unroll 4
    for (int k = 0; k < 128; k++) {
        ulonglong2 b = *(ulonglong2*)&B2[k][c2];
#pragma unroll
        for (int i = 0; i < 8; i++) {
            u64 ad = dup2(H[r0 + i][k]);
            fma2(acc2[i][0], ad, b.x); fma2(acc2[i][1], ad, b.y);
        }
    }
#pragma unroll
    for (int i = 0; i < 8; i++)
        *(float4*)&We[(e0 + r0 + i) * 64 + c2] =
            make_float4(lo2(acc2[i][0]), hi2(acc2[i][0]), lo2(acc2[i][1]), hi2(acc2[i][1]));
}

// ---------------- tensor product + SO3 layernorm per edge ----------------
__global__ void __launch_bounds__(256) k_tp(const float* __restrict__ equiv,
                                            const float* __restrict__ envn,
                                            const int* __restrict__ src,
                                            const float* __restrict__ gtp,
                                            float* __restrict__ tpo,
                                            float* __restrict__ s2) {
    const size_t e = (size_t)blockIdx.x * 8 + (threadIdx.x >> 5);
    const int m = threadIdx.x & 31;
    const int sn = src[e];
    float4 a = *(const float4*)&equiv[e * 128 + 4 * m];
    float4 b = *(const float4*)&envn[(size_t)sn * 128 + 4 * m];
    float o0 = a.x * b.x;
    float o1 = (a.y * b.y + a.z * b.z + a.w * b.w) * 0.57735026918962576f;
    float o2 = a.x * b.y, o3 = a.x * b.z, o4 = a.x * b.w;
    float o5 = a.y * b.x, o6 = a.z * b.x, o7 = a.w * b.x;
    float p0 = o0 * o0, p1 = o1 * o1;
    float p2 = o2 * o2 + o3 * o3 + o4 * o4;
    float p3 = o5 * o5 + o6 * o6 + o7 * o7;
#pragma unroll
    for (int o = 16; o; o >>= 1) {
        p0 += __shfl_xor_sync(0xffffffffu, p0, o);
        p1 += __shfl_xor_sync(0xffffffffu, p1, o);
        p2 += __shfl_xor_sync(0xffffffffu, p2, o);
        p3 += __shfl_xor_sync(0xffffffffu, p3, o);
    }
    float c0 = rsqrtf(p0 * (1.f / 32.f) + 1e-6f) * gtp[4 * m + 0];
    float c1 = rsqrtf(p1 * (1.f / 32.f) + 1e-6f) * gtp[4 * m + 1];
    float c2 = rsqrtf(p2 * (1.f / 96.f) + 1e-6f) * gtp[4 * m + 2];
    float c3 = rsqrtf(p3 * (1.f / 96.f) + 1e-6f) * gtp[4 * m + 3];
    o0 *= c0; o1 *= c1; o2 *= c2; o3 *= c2; o4 *= c2; o5 *= c3; o6 *= c3; o7 *= c3;
    *(float4*)&tpo[e * 256 + m * 8]     = make_float4(o0, o1, o2, o3);
    *(float4*)&tpo[e * 256 + m * 8 + 4] = make_float4(o4, o5, o6, o7);
    *(float2*)&s2[e * 64 + 2 * m] = make_float2(o0, o1);
}

// ---------------- fused p MLP + residual outputs ----------------
__global__ void __launch_bounds__(256) g_p_f(const float* __restrict__ X64,
                                             const float* __restrict__ C32,
                                             const float* __restrict__ W1,
                                             const float* __restrict__ b1,
                                             const float* __restrict__ W2,
                                             const float* __restrict__ scal,
                                             const float* __restrict__ equiv,
                                             const float* __restrict__ tpo,
                                             const float* __restrict__ ruc,
                                             float* __restrict__ outs,
                                             float* __restrict__ oute) {
    extern __shared__ float sm[];
    float (*As)[132] = (float(*)[132])sm;
    float (*Bs)[132] = (float(*)[132])(sm + R2_OFF);
    float (*H)[132]  = (float(*)[132])sm;
    float (*B2)[68]  = (float(*)[68])(sm + R2_OFF);
    const int t = threadIdx.x;
    const size_t e0 = (size_t)blockIdx.x * 128;
    for (int i = t; i < 96 * 32; i += 256) {
        int k = i >> 5, c = (i & 31) * 4;
        *(float4*)&Bs[k][c] = *(const float4*)&W1[k * 128 + c];
    }
    for (int i = t; i < 128 * 16; i += 256) {
        int r = i >> 4, k = (i & 15) * 4;
        float4 v = *(const float4*)&X64[(e0 + r) * 64 + k];
        As[k][r] = v.x; As[k + 1][r] = v.y; As[k + 2][r] = v.z; As[k + 3][r] = v.w;
    }
    for (int i = t; i < 128 * 8; i += 256) {
        int r = i >> 3, k = (i & 7) * 4;
        float4 v = *(const float4*)&C32[(e0 + r) * 32 + k];
        As[64 + k][r] = v.x; As[65 + k][r] = v.y; As[66 + k][r] = v.z; As[67 + k][r] = v.w;
    }
    __syncthreads();
    const int tx = t & 15, ty = t >> 4;
    const int c0 = tx * 8, r0 = ty * 8;
    u64 acc[8][4];
#pragma unroll
    for (int i = 0; i < 8; i++)
#pragma unroll
        for (int j = 0; j < 4; j++) acc[i][j] = 0ull;
#pragma unroll 4
    for (int k = 0; k < 96; k++) {
        float4 a0 = *(float4*)&As[k][r0], a1 = *(float4*)&As[k][r0 + 4];
        ulonglong2 b0 = *(ulonglong2*)&Bs[k][c0];
        ulonglong2 b1 = *(ulonglong2*)&Bs[k][c0 + 4];
        float av[8] = {a0.x, a0.y, a0.z, a0.w, a1.x, a1.y, a1.z, a1.w};
#pragma unroll
        for (int i = 0; i < 8; i++) {
            u64 ad = dup2(av[i]);
            fma2(acc[i][0], ad, b0.x); fma2(acc[i][1], ad, b0.y);
            fma2(acc[i][2], ad, b1.x); fma2(acc[i][3], ad, b1.y);
        }
    }
    float bb[8];
#pragma unroll
    for (int j = 0; j < 8; j++) bb[j] = b1[c0 + j];
    float hbuf[8][8];
#pragma unroll
    for (int i = 0; i < 8; i++)
#pragma unroll
        for (int j = 0; j < 4; j++) {
            hbuf[i][2 * j]     = silu_f(lo2(acc[i][j]) + bb[2 * j]);
            hbuf[i][2 * j + 1] = silu_f(hi2(acc[i][j]) + bb[2 * j + 1]);
        }
    __syncthreads();
#pragma unroll
    for (int i = 0; i < 8; i++) {
        *(float4*)&H[r0 + i][c0]     = make_float4(hbuf[i][0], hbuf[i][1], hbuf[i][2], hbuf[i][3]);
        *(float4*)&H[r0 + i][c0 + 4] = make_float4(hbuf[i][4], hbuf[i][5], hbuf[i][6], hbuf[i][7]);
    }
    float r = ruc[0];
    float c_old = rsqrtf(r * r + 1.0f);
    float c_new = r * c_old;
    const int c2 = tx * 4;
    for (int ch = 0; ch < 3; ch++) {
        __syncthreads();
        for (int i = t; i < 128 * 16; i += 256) {
            int k = i >> 4, c = (i & 15) * 4;
            *(float4*)&B2[k][c] = *(const float4*)&W2[(size_t)k * 192 + ch * 64 + c];
        }
        __syncthreads();
        u64 acc2[8][2];
#pragma unroll
        for (int i = 0; i < 8; i++) { acc2[i][0] = 0ull; acc2[i][1] = 0ull; }
#pragma unroll 4
        for (int k = 0; k < 128; k++) {
            ulonglong2 b = *(ulonglong2*)&B2[k][c2];
#pragma unroll
            for (int i = 0; i < 8; i++) {
                u64 ad = dup2(H[r0 + i][k]);
                fma2(acc2[i][0], ad, b.x); fma2(acc2[i][1], ad, b.y);
            }
        }
        if (ch == 0) {
#pragma unroll
            for (int i = 0; i < 8; i++) {
                size_t e = e0 + r0 + i;
                float4 s0 = *(const float4*)&scal[e * 64 + c2];
                *(float4*)&outs[e * 64 + c2] = make_float4(
                    c_old * s0.x + c_new * lo2(acc2[i][0]),
                    c_old * s0.y + c_new * hi2(acc2[i][0]),
                    c_old * s0.z + c_new * lo2(acc2[i][1]),
                    c_old * s0.w + c_new * hi2(acc2[i][1]));
            }
        } else {
            const int mm = (ch - 1) * 16 + tx;
#pragma unroll
            for (int i = 0; i < 8; i++) {
                size_t e = e0 + r0 + i;
                float pw0 = lo2(acc2[i][0]), pw1 = hi2(acc2[i][0]);
                float pw2 = lo2(acc2[i][1]), pw3 = hi2(acc2[i][1]);
                const float4* tp = (const float4*)&tpo[e * 256 + mm * 8];
                float4 t0 = tp[0], t1 = tp[1];
                float ns  = pw0 * t0.x + pw1 * t0.y;
                float nv0 = pw2 * t0.z + pw3 * t1.y;
                float nv1 = pw2 * t0.w + pw3 * t1.z;
                float nv2 = pw2 * t1.x + pw3 * t1.w;
                float4 old = *(const float4*)&equiv[e * 128 + 4 * mm];
                *(float4*)&oute[e * 128 + 4 * mm] = make_float4(
                    c_old * old.x + c_new * ns,
                    c_old * old.y + c_new * nv0,
                    c_old * old.z + c_new * nv1,
                    c_old * old.w + c_new * nv2);
            }
        }
    }
}

// ---------------- launch ----------------
extern "C" void kernel_launch(void* const* d_in, const int* in_sizes, int n_in,
                              void* d_out, int out_size) {
    const float* node_attrs = (const float*)d_in[0];
    const float* scal  = (const float*)d_in[1];
    const float* equiv = (const float*)d_in[2];
    const float* cond  = (const float*)d_in[3];
    const float* ruc   = (const float*)d_in[4];
    const float* W1    = (const float*)d_in[5];
    const float* b1    = (const float*)d_in[6];
    const float* W2    = (const float*)d_in[7];
    const float* Wq    = (const float*)d_in[8];
    const float* Wk    = (const float*)d_in[9];
    const float* genv  = (const float*)d_in[10];
    const float* gtp   = (const float*)d_in[11];
    const float* Wp1   = (const float*)d_in[12];
    const float* bp1   = (const float*)d_in[13];
    const float* Wp2   = (const float*)d_in[14];
    const int*   src   = (const int*)d_in[15];

    const int N = in_sizes[0] / 64;
    const int E = in_sizes[1] / 64;
    float* outs = (float*)d_out;
    float* oute = outs + (size_t)E * 64;

    float *pM, *pP, *penv, *pWe, *ptpo, *ps2;
    int *pcnt, *poffs, *pwo, *pelist;
    cudaGetSymbolAddress((void**)&pM,    g_M);
    cudaGetSymbolAddress((void**)&pP,    g_P);
    cudaGetSymbolAddress((void**)&penv,  g_envn);
    cudaGetSymbolAddress((void**)&pWe,   g_We);
    cudaGetSymbolAddress((void**)&ptpo,  g_tpo);
    cudaGetSymbolAddress((void**)&ps2,   g_s2);
    cudaGetSymbolAddress((void**)&pcnt,  g_cnt);
    cudaGetSymbolAddress((void**)&poffs, g_offs);
    cudaGetSymbolAddress((void**)&pwo,   g_wo);
    cudaGetSymbolAddress((void**)&pelist, g_elist);

    const int SMK = (2 * 64 * 132) * 4;

    cudaFuncSetAttribute(g_pmat,  cudaFuncAttributeMaxDynamicSharedMemorySize, SMK);
    cudaFuncSetAttribute(g_env_f, cudaFuncAttributeMaxDynamicSharedMemorySize, SMF);
    cudaFuncSetAttribute(g_p_f,   cudaFuncAttributeMaxDynamicSharedMemorySize, SMF);

    cudaMemsetAsync(pcnt, 0, (size_t)N * sizeof(int));
    k_count<<<E / 256, 256>>>(src, pcnt);
    k_scan<<<1, 1024>>>(pcnt, poffs, pwo);
    k_scatter<<<E / 256, 256>>>(src, pwo, pelist);

    k_M<<<64, 256>>>(Wq, Wk, pM);
    g_pmat<<<dim3(N / 128, 16), 256, SMK>>>(node_attrs, pM, pP);
    g_env_f<<<E / 128, 256, SMF>>>(scal, cond, W1, b1, W2, pWe);
    k_attn<<<N / 4, 128>>>(scal, pP, pWe, equiv, poffs, pelist, genv, penv);
    k_tp<<<E / 8, 256>>>(equiv, penv, src, gtp, ptpo, ps2);
    g_p_f<<<E / 128, 256, SMF>>>(ps2, cond, Wp1, bp1, Wp2, scal, equiv, ptpo, ruc, outs, oute);
}

// round 10
// speedup vs baseline: 1.0461x; 1.0461x over previous
#include <cuda_runtime.h>

// ---------------- fixed problem shape ----------------
#define E_TOT 262144
#define N_TOT 16384

// ---------------- device scratch (static, no allocation) ----------------
__device__ float g_M   [64 * 2048];                 // Wq(x)Wk contraction
__device__ float g_P   [(size_t)N_TOT * 2048];      // per-node logit matrix
__device__ float g_envn[(size_t)N_TOT * 128];
__device__ float g_We  [(size_t)E_TOT * 64];
__device__ float g_s2  [(size_t)E_TOT * 64];
__device__ float g_ninv[(size_t)E_TOT * 4];
__device__ int   g_cnt [N_TOT];
__device__ int   g_offs[N_TOT + 1];
__device__ int   g_wo  [N_TOT];
__device__ int   g_elist[E_TOT];

typedef unsigned long long u64;

static __device__ __forceinline__ u64 dup2(float a) {
    u64 r; asm("mov.b64 %0, {%1, %1};" : "=l"(r) : "f"(a)); return r;
}
static __device__ __forceinline__ void fma2(u64& acc, u64 a, u64 b) {
    asm("fma.rn.f32x2 %0, %1, %2, %0;" : "+l"(acc) : "l"(a), "l"(b));
}
static __device__ __forceinline__ float lo2(u64 v) { return __uint_as_float((unsigned)v); }
static __device__ __forceinline__ float hi2(u64 v) { return __uint_as_float((unsigned)(v >> 32)); }
static __device__ __forceinline__ float silu_f(float v) { return v / (1.0f + __expf(-v)); }

// ---------------- CSR build ----------------
__global__ void k_count(const int* __restrict__ src, int* __restrict__ cnt) {
    int e = blockIdx.x * 256 + threadIdx.x;
    atomicAdd(&cnt[src[e]], 1);
}

__global__ void __launch_bounds__(1024) k_scan(const int* __restrict__ cnt,
                                               int* __restrict__ offs,
                                               int* __restrict__ wo) {
    __shared__ int part[1024];
    const int t = threadIdx.x;
    const int base = t * 16;
    int loc[16];
    int s = 0;
#pragma unroll
    for (int i = 0; i < 16; i++) { loc[i] = s; s += cnt[base + i]; }
    part[t] = s;
    __syncthreads();
    for (int d = 1; d < 1024; d <<= 1) {
        int v = part[t];
        int u = (t >= d) ? part[t - d] : 0;
        __syncthreads();
        part[t] = v + u;
        __syncthreads();
    }
    int tOff = part[t] - s;
#pragma unroll
    for (int i = 0; i < 16; i++) {
        int o = tOff + loc[i];
        offs[base + i] = o;
        wo[base + i] = o;
    }
    if (t == 1023) offs[N_TOT] = part[1023];
}

__global__ void k_scatter(const int* __restrict__ src, int* __restrict__ wo,
                          int* __restrict__ elist) {
    int e = blockIdx.x * 256 + threadIdx.x;
    int pos = atomicAdd(&wo[src[e]], 1);
    elist[pos] = e;
}

// ---------------- K0: M[c, j*32+m] = sum_d Wq[c,16m+d]*Wk[j,16m+d] ----------------
__global__ void k_M(const float* __restrict__ Wq, const float* __restrict__ Wk,
                    float* __restrict__ M) {
    const int o = (blockIdx.x * 256 + threadIdx.x) * 4;   // 131072 outputs
    const int c = o >> 11;
    const int j = (o & 2047) >> 5;
    const int m0 = o & 31;
    const float* wq = Wq + (size_t)c * 512;
    const float* wk = Wk + (size_t)j * 512;
    float r[4];
#pragma unroll
    for (int q = 0; q < 4; q++) {
        int m = m0 + q;
        float s = 0.f;
#pragma unroll
        for (int d = 0; d < 16; d++) s = fmaf(wq[16 * m + d], wk[16 * m + d], s);
        r[q] = s;
    }
    *(float4*)&M[(size_t)c * 2048 + j * 32 + m0] = make_float4(r[0], r[1], r[2], r[3]);
}

// ---------------- G1: P = node_attrs @ M   [16384,64]x[64,2048] ----------------
__global__ void __launch_bounds__(256) g_pmat(const float* __restrict__ A,
                                              const float* __restrict__ M,
                                              float* __restrict__ P) {
    extern __shared__ float sm[];
    float (*As)[132] = (float(*)[132])sm;
    float (*Bs)[132] = (float(*)[132])(sm + 64 * 132);
    const int t = threadIdx.x;
    const size_t n0 = (size_t)blockIdx.x * 128;
    const int cb = blockIdx.y * 128;
    for (int i = t; i < 64 * 32; i += 256) {
        int k = i >> 5, c = (i & 31) * 4;
        *(float4*)&Bs[k][c] = *(const float4*)&M[(size_t)k * 2048 + cb + c];
    }
    for (int i = t; i < 128 * 16; i += 256) {
        int r = i >> 4, k = (i & 15) * 4;
        float4 v = *(const float4*)&A[(n0 + r) * 64 + k];
        As[k][r] = v.x; As[k + 1][r] = v.y; As[k + 2][r] = v.z; As[k + 3][r] = v.w;
    }
    __syncthreads();
    const int tx = t & 15, ty = t >> 4;
    const int c0 = tx * 8, r0 = ty * 8;
    u64 acc[8][4];
#pragma unroll
    for (int i = 0; i < 8; i++)
#pragma unroll
        for (int j = 0; j < 4; j++) acc[i][j] = 0ull;
#pragma unroll 4
    for (int k = 0; k < 64; k++) {
        float4 a0 = *(float4*)&As[k][r0], a1 = *(float4*)&As[k][r0 + 4];
        ulonglong2 b0 = *(ulonglong2*)&Bs[k][c0];
        ulonglong2 b1 = *(ulonglong2*)&Bs[k][c0 + 4];
        float av[8] = {a0.x, a0.y, a0.z, a0.w, a1.x, a1.y, a1.z, a1.w};
#pragma unroll
        for (int i = 0; i < 8; i++) {
            u64 ad = dup2(av[i]);
            fma2(acc[i][0], ad, b0.x); fma2(acc[i][1], ad, b0.y);
            fma2(acc[i][2], ad, b1.x); fma2(acc[i][3], ad, b1.y);
        }
    }
#pragma unroll
    for (int i = 0; i < 8; i++) {
        size_t n = n0 + r0 + i;
        *(float4*)&P[n * 2048 + cb + c0] =
            make_float4(lo2(acc[i][0]), hi2(acc[i][0]), lo2(acc[i][1]), hi2(acc[i][1]));
        *(float4*)&P[n * 2048 + cb + c0 + 4] =
            make_float4(lo2(acc[i][2]), hi2(acc[i][2]), lo2(acc[i][3]), hi2(acc[i][3]));
    }
}

// ---------------- fused attention: one warp per node ----------------
__global__ void __launch_bounds__(128) k_attn(const float* __restrict__ scal,
                                              const float* __restrict__ P,
                                              const float* __restrict__ We,
                                              const float* __restrict__ equiv,
                                              const int* __restrict__ offs,
                                              const int* __restrict__ elist,
                                              const float* __restrict__ genv,
                                              float* __restrict__ envn) {
    const int n = blockIdx.x * 4 + (threadIdx.x >> 5);
    const int m = threadIdx.x & 31;
    const int o0 = offs[n], o1 = offs[n + 1];
    if (o0 == o1) return;
    float Preg[64];
    const float* p = P + (size_t)n * 2048 + m;
#pragma unroll
    for (int j = 0; j < 64; j++) Preg[j] = __ldg(&p[j * 32]);

    float den = 0.f, x0 = 0.f, x1 = 0.f, x2 = 0.f, x3 = 0.f;

    int e = elist[o0];
    float slo = scal[(size_t)e * 64 + m];
    float shi = scal[(size_t)e * 64 + 32 + m];
    float2 w  = *(const float2*)&We[(size_t)e * 64 + 2 * m];
    float4 ev = *(const float4*)&equiv[(size_t)e * 128 + 4 * m];
    for (int i = o0; i < o1; i++) {
        float cslo = slo, cshi = shi;
        float2 cw = w; float4 cev = ev;
        if (i + 1 < o1) {
            int en = elist[i + 1];
            slo = scal[(size_t)en * 64 + m];
            shi = scal[(size_t)en * 64 + 32 + m];
            w   = *(const float2*)&We[(size_t)en * 64 + 2 * m];
            ev  = *(const float4*)&equiv[(size_t)en * 128 + 4 * m];
        }
        float a0 = 0.f, a1 = 0.f, a2 = 0.f, a3 = 0.f;
#pragma unroll
        for (int j = 0; j < 32; j += 4) {
            a0 = fmaf(__shfl_sync(0xffffffffu, cslo, j),     Preg[j],     a0);
            a1 = fmaf(__shfl_sync(0xffffffffu, cslo, j + 1), Preg[j + 1], a1);
            a2 = fmaf(__shfl_sync(0xffffffffu, cslo, j + 2), Preg[j + 2], a2);
            a3 = fmaf(__shfl_sync(0xffffffffu, cslo, j + 3), Preg[j + 3], a3);
        }
#pragma unroll
        for (int j = 0; j < 32; j += 4) {
            a0 = fmaf(__shfl_sync(0xffffffffu, cshi, j),     Preg[32 + j],     a0);
            a1 = fmaf(__shfl_sync(0xffffffffu, cshi, j + 1), Preg[33 + j],     a1);
            a2 = fmaf(__shfl_sync(0xffffffffu, cshi, j + 2), Preg[34 + j],     a2);
            a3 = fmaf(__shfl_sync(0xffffffffu, cshi, j + 3), Preg[35 + j],     a3);
        }
        float lg = (a0 + a1 + a2 + a3) * 0.25f;
        lg = fminf(5.0f, fmaxf(-5.0f, lg));
        float el = __expf(lg);
        den += el;
        float w0 = cw.x * el, w1 = cw.y * el;
        x0 = fmaf(cev.x, w0, x0);
        x1 = fmaf(cev.y, w1, x1);
        x2 = fmaf(cev.z, w1, x2);
        x3 = fmaf(cev.w, w1, x3);
    }
    float inv = __frcp_rn(den);
    x0 *= inv; x1 *= inv; x2 *= inv; x3 *= inv;
    float s0 = x0 * x0;
    float s1 = x1 * x1 + x2 * x2 + x3 * x3;
#pragma unroll
    for (int o = 16; o; o >>= 1) {
        s0 += __shfl_xor_sync(0xffffffffu, s0, o);
        s1 += __shfl_xor_sync(0xffffffffu, s1, o);
    }
    float i0 = rsqrtf(s0 * (1.f / 32.f) + 1e-6f);
    float i1 = rsqrtf(s1 * (1.f / 96.f) + 1e-6f);
    float g0 = genv[2 * m], g1 = genv[2 * m + 1];
    *(float4*)&envn[(size_t)n * 128 + 4 * m] =
        make_float4(x0 * i0 * g0, x1 * i1 * g1, x2 * i1 * g1, x3 * i1 * g1);
}

// ---------------- fused env MLP: We = silu([scal|cond]@W1+b1) @ W2 ----------------
#define R2_OFF 16896
#define SMF ((16896 + 12672) * 4)
// g_p_f extra region: src[128] + ninv[128][4]
#define EX_OFF (16896 + 12672)
#define SMF2 ((EX_OFF + 128 + 512) * 4)

__global__ void __launch_bounds__(256) g_env_f(const float* __restrict__ X64,
                                               const float* __restrict__ C32,
                                               const float* __restrict__ W1,
                                               const float* __restrict__ b1,
                                               const float* __restrict__ W2,
                                               float* __restrict__ We) {
    extern __shared__ float sm[];
    float (*As)[132] = (float(*)[132])sm;
    float (*Bs)[132] = (float(*)[132])(sm + R2_OFF);
    float (*H)[132]  = (float(*)[132])sm;
    float (*B2)[68]  = (float(*)[68])(sm + R2_OFF);
    const int t = threadIdx.x;
    const size_t e0 = (size_t)blockIdx.x * 128;
    for (int i = t; i < 96 * 32; i += 256) {
        int k = i >> 5, c = (i & 31) * 4;
        *(float4*)&Bs[k][c] = *(const float4*)&W1[k * 128 + c];
    }
    for (int i = t; i < 128 * 16; i += 256) {
        int r = i >> 4, k = (i & 15) * 4;
        float4 v = *(const float4*)&X64[(e0 + r) * 64 + k];
        As[k][r] = v.x; As[k + 1][r] = v.y; As[k + 2][r] = v.z; As[k + 3][r] = v.w;
    }
    for (int i = t; i < 128 * 8; i += 256) {
        int r = i >> 3, k = (i & 7) * 4;
        float4 v = *(const float4*)&C32[(e0 + r) * 32 + k];
        As[64 + k][r] = v.x; As[65 + k][r] = v.y; As[66 + k][r] = v.z; As[67 + k][r] = v.w;
    }
    __syncthreads();
    const int tx = t & 15, ty = t >> 4;
    const int c0 = tx * 8, r0 = ty * 8;
    u64 acc[8][4];
#pragma unroll
    for (int i = 0; i < 8; i++)
#pragma unroll
        for (int j = 0; j < 4; j++) acc[i][j] = 0ull;
#pragma unroll 4
    for (int k = 0; k < 96; k++) {
        float4 a0 = *(float4*)&As[k][r0], a1 = *(float4*)&As[k][r0 + 4];
        ulonglong2 b0 = *(ulonglong2*)&Bs[k][c0];
        ulonglong2 b1 = *(ulonglong2*)&Bs[k][c0 + 4];
        float av[8] = {a0.x, a0.y, a0.z, a0.w, a1.x, a1.y, a1.z, a1.w};
#pragma unroll
        for (int i = 0; i < 8; i++) {
            u64 ad = dup2(av[i]);
            fma2(acc[i][0], ad, b0.x); fma2(acc[i][1], ad, b0.y);
            fma2(acc[i][2], ad, b1.x); fma2(acc[i][3], ad, b1.y);
        }
    }
    float bb[8];
#pragma unroll
    for (int j = 0; j < 8; j++) bb[j] = b1[c0 + j];
    float hbuf[8][8];
#pragma unroll
    for (int i = 0; i < 8; i++)
#pragma unroll
        for (int j = 0; j < 4; j++) {
            hbuf[i][2 * j]     = silu_f(lo2(acc[i][j]) + bb[2 * j]);
            hbuf[i][2 * j + 1] = silu_f(hi2(acc[i][j]) + bb[2 * j + 1]);
        }
    __syncthreads();
#pragma unroll
    for (int i = 0; i < 8; i++) {
        *(float4*)&H[r0 + i][c0]     = make_float4(hbuf[i][0], hbuf[i][1], hbuf[i][2], hbuf[i][3]);
        *(float4*)&H[r0 + i][c0 + 4] = make_float4(hbuf[i][4], hbuf[i][5], hbuf[i][6], hbuf[i][7]);
    }
    for (int i = t; i < 128 * 16; i += 256) {
        int k = i >> 4, c = (i & 15) * 4;
        *(float4*)&B2[k][c] = *(const float4*)&W2[k * 64 + c];
    }
    __syncthreads();
    const int c2 = tx * 4;
    u64 acc2[8][2];
#pragma unroll
    for (int i = 0; i < 8; i++) { acc2[i][0] = 0ull; acc2[i][1] = 0ull; }
#pragma unroll 4
    for (int k = 0; k < 128; k++) {
        ulonglong2 b = *(ulonglong2*)&B2[k][c2];
#pragma unroll
        for (int i = 0; i < 8; i++) {
            u64 ad = dup2(H[r0 + i][k]);
            fma2(acc2[i][0], ad, b.x); fma2(acc2[i][1], ad, b.y);
        }
    }
#pragma unroll
    for (int i = 0; i < 8; i++)
        *(float4*)&We[(e0 + r0 + i) * 64 + c2] =
            make_float4(lo2(acc2[i][0]), hi2(acc2[i][0]), lo2(acc2[i][1]), hi2(acc2[i][1]));
}

// ---------------- tensor product scalars + LN coefficients per edge ----------------
// writes s2 [E,64] (LN-normalized scalar channels) and ninv [E,4] (raw rsqrt coeffs)
__global__ void __launch_bounds__(256) k_tp(const float* __restrict__ equiv,
                                            const float* __restrict__ envn,
                                            const int* __restrict__ src,
                                            const float* __restrict__ gtp,
                                            float* __restrict__ s2,
                                            float* __restrict__ ninv) {
    const size_t e = (size_t)blockIdx.x * 8 + (threadIdx.x >> 5);
    const int m = threadIdx.x & 31;
    const int sn = src[e];
    float4 a = *(const float4*)&equiv[e * 128 + 4 * m];
    float4 b = *(const float4*)&envn[(size_t)sn * 128 + 4 * m];
    float o0 = a.x * b.x;
    float o1 = (a.y * b.y + a.z * b.z + a.w * b.w) * 0.57735026918962576f;
    float o2 = a.x * b.y, o3 = a.x * b.z, o4 = a.x * b.w;
    float o5 = a.y * b.x, o6 = a.z * b.x, o7 = a.w * b.x;
    float p0 = o0 * o0, p1 = o1 * o1;
    float p2 = o2 * o2 + o3 * o3 + o4 * o4;
    float p3 = o5 * o5 + o6 * o6 + o7 * o7;
#pragma unroll
    for (int o = 16; o; o >>= 1) {
        p0 += __shfl_xor_sync(0xffffffffu, p0, o);
        p1 += __shfl_xor_sync(0xffffffffu, p1, o);
        p2 += __shfl_xor_sync(0xffffffffu, p2, o);
        p3 += __shfl_xor_sync(0xffffffffu, p3, o);
    }
    float i0 = rsqrtf(p0 * (1.f / 32.f) + 1e-6f);
    float i1 = rsqrtf(p1 * (1.f / 32.f) + 1e-6f);
    float i2 = rsqrtf(p2 * (1.f / 96.f) + 1e-6f);
    float i3 = rsqrtf(p3 * (1.f / 96.f) + 1e-6f);
    float c0 = i0 * gtp[4 * m + 0];
    float c1 = i1 * gtp[4 * m + 1];
    *(float2*)&s2[e * 64 + 2 * m] = make_float2(o0 * c0, o1 * c1);
    if (m == 0) *(float4*)&ninv[e * 4] = make_float4(i0, i1, i2, i3);
}

// ---------------- fused p MLP + tp recompute + residual outputs ----------------
__global__ void __launch_bounds__(256) g_p_f(const float* __restrict__ X64,
                                             const float* __restrict__ C32,
                                             const float* __restrict__ W1,
                                             const float* __restrict__ b1,
                                             const float* __restrict__ W2,
                                             const float* __restrict__ scal,
                                             const float* __restrict__ equiv,
                                             const float* __restrict__ envn,
                                             const int* __restrict__ src,
                                             const float* __restrict__ gtp,
                                             const float* __restrict__ ninv,
                                             const float* __restrict__ ruc,
                                             float* __restrict__ outs,
                                             float* __restrict__ oute) {
    extern __shared__ float sm[];
    float (*As)[132] = (float(*)[132])sm;
    float (*Bs)[132] = (float(*)[132])(sm + R2_OFF);
    float (*H)[132]  = (float(*)[132])sm;
    float (*B2)[68]  = (float(*)[68])(sm + R2_OFF);
    int*   s_src  = (int*)(sm + EX_OFF);
    float (*s_ni)[4] = (float(*)[4])(sm + EX_OFF + 128);
    const int t = threadIdx.x;
    const size_t e0 = (size_t)blockIdx.x * 128;
    if (t < 128) {
        s_src[t] = src[e0 + t];
        *(float4*)&s_ni[t][0] = *(const float4*)&ninv[(e0 + t) * 4];
    }
    for (int i = t; i < 96 * 32; i += 256) {
        int k = i >> 5, c = (i & 31) * 4;
        *(float4*)&Bs[k][c] = *(const float4*)&W1[k * 128 + c];
    }
    for (int i = t; i < 128 * 16; i += 256) {
        int r = i >> 4, k = (i & 15) * 4;
        float4 v = *(const float4*)&X64[(e0 + r) * 64 + k];
        As[k][r] = v.x; As[k + 1][r] = v.y; As[k + 2][r] = v.z; As[k + 3][r] = v.w;
    }
    for (int i = t; i < 128 * 8; i += 256) {
        int r = i >> 3, k = (i & 7) * 4;
        float4 v = *(const float4*)&C32[(e0 + r) * 32 + k];
        As[64 + k][r] = v.x; As[65 + k][r] = v.y; As[66 + k][r] = v.z; As[67 + k][r] = v.w;
    }
    __syncthreads();
    const int tx = t & 15, ty = t >> 4;
    const int c0 = tx * 8, r0 = ty * 8;
    u64 acc[8][4];
#pragma unroll
    for (int i = 0; i < 8; i++)
#pragma unroll
        for (int j = 0; j < 4; j++) acc[i][j] = 0ull;
#pragma unroll 4
    for (int k = 0; k < 96; k++) {
        float4 a0 = *(float4*)&As[k][r0], a1 = *(float4*)&As[k][r0 + 4];
        ulonglong2 b0 = *(ulonglong2*)&Bs[k][c0];
        ulonglong2 b1 = *(ulonglong2*)&Bs[k][c0 + 4];
        float av[8] = {a0.x, a0.y, a0.z, a0.w, a1.x, a1.y, a1.z, a1.w};
#pragma unroll
        for (int i = 0; i < 8; i++) {
            u64 ad = dup2(av[i]);
            fma2(acc[i][0], ad, b0.x); fma2(acc[i][1], ad, b0.y);
            fma2(acc[i][2], ad, b1.x); fma2(acc[i][3], ad, b1.y);
        }
    }
    float bb[8];
#pragma unroll
    for (int j = 0; j < 8; j++) bb[j] = b1[c0 + j];
    float hbuf[8][8];
#pragma unroll
    for (int i = 0; i < 8; i++)
#pragma unroll
        for (int j = 0; j < 4; j++) {
            hbuf[i][2 * j]     = silu_f(lo2(acc[i][j]) + bb[2 * j]);
            hbuf[i][2 * j + 1] = silu_f(hi2(acc[i][j]) + bb[2 * j + 1]);
        }
    __syncthreads();
#pragma unroll
    for (int i = 0; i < 8; i++) {
        *(float4*)&H[r0 + i][c0]     = make_float4(hbuf[i][0], hbuf[i][1], hbuf[i][2], hbuf[i][3]);
        *(float4*)&H[r0 + i][c0 + 4] = make_float4(hbuf[i][4], hbuf[i][5], hbuf[i][6], hbuf[i][7]);
    }
    float r = ruc[0];
    float c_old = rsqrtf(r * r + 1.0f);
    float c_new = r * c_old;
    const int c2 = tx * 4;
    for (int ch = 0; ch < 3; ch++) {
        __syncthreads();
        for (int i = t; i < 128 * 16; i += 256) {
            int k = i >> 4, c = (i & 15) * 4;
            *(float4*)&B2[k][c] = *(const float4*)&W2[(size_t)k * 192 + ch * 64 + c];
        }
        __syncthreads();
        u64 acc2[8][2];
#pragma unroll
        for (int i = 0; i < 8; i++) { acc2[i][0] = 0ull; acc2[i][1] = 0ull; }
#pragma unroll 4
        for (int k = 0; k < 128; k++) {
            ulonglong2 b = *(ulonglong2*)&B2[k][c2];
#pragma unroll
            for (int i = 0; i < 8; i++) {
                u64 ad = dup2(H[r0 + i][k]);
                fma2(acc2[i][0], ad, b.x); fma2(acc2[i][1], ad, b.y);
            }
        }
        if (ch == 0) {
#pragma unroll
            for (int i = 0; i < 8; i++) {
                size_t e = e0 + r0 + i;
                float4 s0 = *(const float4*)&scal[e * 64 + c2];
                *(float4*)&outs[e * 64 + c2] = make_float4(
                    c_old * s0.x + c_new * lo2(acc2[i][0]),
                    c_old * s0.y + c_new * hi2(acc2[i][0]),
                    c_old * s0.z + c_new * lo2(acc2[i][1]),
                    c_old * s0.w + c_new * hi2(acc2[i][1]));
            }
        } else {
            const int mm = (ch - 1) * 16 + tx;
            float4 gt = *(const float4*)&gtp[4 * mm];
#pragma unroll
            for (int i = 0; i < 8; i++) {
                size_t e = e0 + r0 + i;
                const int sn = s_src[r0 + i];
                float4 ni = *(float4*)&s_ni[r0 + i][0];
                float4 a = *(const float4*)&equiv[e * 128 + 4 * mm];
                float4 b = *(const float4*)&envn[(size_t)sn * 128 + 4 * mm];
                // recompute normalized tp channels for this (e, mm)
                float cc0 = ni.x * gt.x, cc1 = ni.y * gt.y;
                float cc2 = ni.z * gt.z, cc3 = ni.w * gt.w;
                float o0 = (a.x * b.x) * cc0;
                float o1 = ((a.y * b.y + a.z * b.z + a.w * b.w) * 0.57735026918962576f) * cc1;
                float o2 = (a.x * b.y) * cc2, o3 = (a.x * b.z) * cc2, o4 = (a.x * b.w) * cc2;
                float o5 = (a.y * b.x) * cc3, o6 = (a.z * b.x) * cc3, o7 = (a.w * b.x) * cc3;
                float pw0 = lo2(acc2[i][0]), pw1 = hi2(acc2[i][0]);
                float pw2 = lo2(acc2[i][1]), pw3 = hi2(acc2[i][1]);
                float ns  = pw0 * o0 + pw1 * o1;
                float nv0 = pw2 * o2 + pw3 * o5;
                float nv1 = pw2 * o3 + pw3 * o6;
                float nv2 = pw2 * o4 + pw3 * o7;
                *(float4*)&oute[e * 128 + 4 * mm] = make_float4(
                    c_old * a.x + c_new * ns,
                    c_old * a.y + c_new * nv0,
                    c_old * a.z + c_new * nv1,
                    c_old * a.w + c_new * nv2);
            }
        }
    }
}

// ---------------- launch ----------------
extern "C" void kernel_launch(void* const* d_in, const int* in_sizes, int n_in,
                              void* d_out, int out_size) {
    const float* node_attrs = (const float*)d_in[0];
    const float* scal  = (const float*)d_in[1];
    const float* equiv = (const float*)d_in[2];
    const float* cond  = (const float*)d_in[3];
    const float* ruc   = (const float*)d_in[4];
    const float* W1    = (const float*)d_in[5];
    const float* b1    = (const float*)d_in[6];
    const float* W2    = (const float*)d_in[7];
    const float* Wq    = (const float*)d_in[8];
    const float* Wk    = (const float*)d_in[9];
    const float* genv  = (const float*)d_in[10];
    const float* gtp   = (const float*)d_in[11];
    const float* Wp1   = (const float*)d_in[12];
    const float* bp1   = (const float*)d_in[13];
    const float* Wp2   = (const float*)d_in[14];
    const int*   src   = (const int*)d_in[15];

    const int N = in_sizes[0] / 64;
    const int E = in_sizes[1] / 64;
    float* outs = (float*)d_out;
    float* oute = outs + (size_t)E * 64;

    float *pM, *pP, *penv, *pWe, *ps2, *pninv;
    int *pcnt, *poffs, *pwo, *pelist;
    cudaGetSymbolAddress((void**)&pM,    g_M);
    cudaGetSymbolAddress((void**)&pP,    g_P);
    cudaGetSymbolAddress((void**)&penv,  g_envn);
    cudaGetSymbolAddress((void**)&pWe,   g_We);
    cudaGetSymbolAddress((void**)&ps2,   g_s2);
    cudaGetSymbolAddress((void**)&pninv, g_ninv);
    cudaGetSymbolAddress((void**)&pcnt,  g_cnt);
    cudaGetSymbolAddress((void**)&poffs, g_offs);
    cudaGetSymbolAddress((void**)&pwo,   g_wo);
    cudaGetSymbolAddress((void**)&pelist, g_elist);

    const int SMK = (2 * 64 * 132) * 4;

    cudaFuncSetAttribute(g_pmat,  cudaFuncAttributeMaxDynamicSharedMemorySize, SMK);
    cudaFuncSetAttribute(g_env_f, cudaFuncAttributeMaxDynamicSharedMemorySize, SMF);
    cudaFuncSetAttribute(g_p_f,   cudaFuncAttributeMaxDynamicSharedMemorySize, SMF2);

    cudaMemsetAsync(pcnt, 0, (size_t)N * sizeof(int));
    k_count<<<E / 256, 256>>>(src, pcnt);
    k_scan<<<1, 1024>>>(pcnt, poffs, pwo);
    k_scatter<<<E / 256, 256>>>(src, pwo, pelist);

    k_M<<<128, 256>>>(Wq, Wk, pM);
    g_pmat<<<dim3(N / 128, 16), 256, SMK>>>(node_attrs, pM, pP);
    g_env_f<<<E / 128, 256, SMF>>>(scal, cond, W1, b1, W2, pWe);
    k_attn<<<N / 4, 128>>>(scal, pP, pWe, equiv, poffs, pelist, genv, penv);
    k_tp<<<E / 8, 256>>>(equiv, penv, src, gtp, ps2, pninv);
    g_p_f<<<E / 128, 256, SMF2>>>(ps2, cond, Wp1, bp1, Wp2, scal, equiv, penv,
                                  src, gtp, pninv, ruc, outs, oute);
}